// round 6
// baseline (speedup 1.0000x reference)
#include <cuda_runtime.h>
#include <math_constants.h>

#define N_POS 3136
#define HW    56
#define MIDC  32
#define HEADS 8
#define INV   0.125f   // 1/sqrt(64), exact power of two

// ---------------- scratch (global, no allocation in kernel_launch) ----------
__device__ float g_q[HEADS * N_POS * MIDC];      // [h][p][m]  fp32
__device__ float g_k[HEADS * N_POS * MIDC];      // tf32-truncated K
__device__ float g_v[HEADS * N_POS * MIDC];      // tf32-truncated V
__device__ float g_rowb[HEADS * N_POS * HW];     // inv-scaled row bias  [h][p][k]
__device__ float g_colb[HEADS * N_POS * HW];     // inv-scaled col bias  [h][p][l]
__device__ float g_o[MIDC * HEADS * N_POS];      // [channel = m*8+h][p]

// ---------------- tf32 helpers ----------------------------------------------
__device__ __forceinline__ unsigned f2tf(float f) {
    unsigned r;
    asm("cvt.rna.tf32.f32 %0, %1;" : "=r"(r) : "f"(f));
    return r;
}
__device__ __forceinline__ void mma_tf32(
    float& d0, float& d1, float& d2, float& d3,
    unsigned a0, unsigned a1, unsigned a2, unsigned a3,
    unsigned b0, unsigned b1)
{
    asm("mma.sync.aligned.m16n8k8.row.col.f32.tf32.tf32.f32 "
        "{%0,%1,%2,%3}, {%4,%5,%6,%7}, {%8,%9}, {%0,%1,%2,%3};"
        : "+f"(d0), "+f"(d1), "+f"(d2), "+f"(d3)
        : "r"(a0), "r"(a1), "r"(a2), "r"(a3), "r"(b0), "r"(b1));
}

#define CP_ASYNC16(dst_smem, src) \
    asm volatile("cp.async.cg.shared.global [%0], [%1], 16;" \
                 :: "r"((unsigned)(dst_smem)), "l"(src))
#define CP_COMMIT()  asm volatile("cp.async.commit_group;")
#define CP_WAIT0()   asm volatile("cp.async.wait_group 0;")

// ---------------- Kernel 1: fused QKV projection ----------------------------
__global__ __launch_bounds__(256) void qkv_kernel(
    const float* __restrict__ x,
    const float* __restrict__ Wq, const float* __restrict__ bq,
    const float* __restrict__ Wk, const float* __restrict__ bk,
    const float* __restrict__ Wv, const float* __restrict__ bv)
{
    __shared__ float Xs[64 * 64];
    __shared__ float Ws[64 * 68];

    const int p0  = blockIdx.x * 64;
    const int by  = blockIdx.y;        // 0..11
    const int mat = by >> 2;           // 0=q 1=k 2=v
    const int dl0 = (by & 3) * 64;

    const float* W    = (mat == 0) ? Wq : (mat == 1) ? Wk : Wv;
    const float* bias = (mat == 0) ? bq : (mat == 1) ? bk : bv;

    const int tid = threadIdx.x;
    for (int i = tid; i < 64 * 16; i += 256) {
        int r = i >> 4, c4 = (i & 15) * 4;
        *(float4*)&Xs[r * 64 + c4] = *(const float4*)&x[r * N_POS + p0 + c4];
        *(float4*)&Ws[r * 68 + c4] = *(const float4*)&W[(dl0 + r) * 64 + c4];
    }
    __syncthreads();

    const int tx = tid & 15, ty = tid >> 4;
    float acc[4][4];
#pragma unroll
    for (int i = 0; i < 4; i++)
#pragma unroll
        for (int j = 0; j < 4; j++) acc[i][j] = 0.f;

#pragma unroll 8
    for (int kk = 0; kk < 64; kk++) {
        float a[4];
#pragma unroll
        for (int i = 0; i < 4; i++) a[i] = Ws[(ty * 4 + i) * 68 + kk];
        float4 b = *(const float4*)&Xs[kk * 64 + tx * 4];
#pragma unroll
        for (int i = 0; i < 4; i++) {
            acc[i][0] += a[i] * b.x;
            acc[i][1] += a[i] * b.y;
            acc[i][2] += a[i] * b.z;
            acc[i][3] += a[i] * b.w;
        }
    }

#pragma unroll
    for (int i = 0; i < 4; i++) {
        int d = dl0 + ty * 4 + i;
        float bv_ = bias[d];
        int h = d & 7, m = d >> 3;       // d = m*8 + h
#pragma unroll
        for (int j = 0; j < 4; j++) {
            int p = p0 + tx * 4 + j;
            float val = acc[i][j] + bv_;
            int idx = (h * N_POS + p) * MIDC + m;
            if (mat == 0) {
                g_q[idx] = val;                         // fp32 Q
            } else if (mat == 1) {
                g_k[idx] = __uint_as_float(f2tf(val));  // tf32 K
            } else {
                g_v[idx] = __uint_as_float(f2tf(val));  // tf32 V
            }
        }
    }
}

// ---------------- Kernel 2: relative-position bias precompute ---------------
__global__ __launch_bounds__(256) void bias_kernel(
    const float* __restrict__ rowT, const float* __restrict__ colT)
{
    int idx = blockIdx.x * 256 + threadIdx.x;
    int h   = idx / (N_POS * 112);
    int rem = idx - h * (N_POS * 112);
    int p   = rem / 112;
    int t   = rem - p * 112;

    const float* Qp = &g_q[(h * N_POS + p) * MIDC];

    if (t < HW) {
        int i = p / HW;
        const float* tr = &rowT[(t - i + 55) * 16];
        float acc = 0.f;
#pragma unroll
        for (int m = 0; m < 16; m++) acc += Qp[m] * tr[m];
        g_rowb[(h * N_POS + p) * HW + t] = acc * INV;
    } else {
        int l = t - HW;
        int j = p % HW;
        const float* tc = &colT[(l - j + 55) * 16];
        float acc = 0.f;
#pragma unroll
        for (int m = 0; m < 16; m++) acc += Qp[16 + m] * tc[m];
        g_colb[(h * N_POS + p) * HW + l] = acc * INV;
    }
}

// ---------------- Kernel 3: tf32 tensor-core flash attention ----------------
// Block = 128 threads = 4 warps; warp w owns query rows [16w, 16w+16).
// Single-precision tf32 everywhere (error budget: |s| small, threshold 1e-3).
// smem (floats), double-buffered K/V tiles:
//   buf b at b*4256:  K [56][36] @ +0,  V [56][40] @ +2016
//   Pm  [64][60] @ 8512
//   rb  [56][64] @ 12352
#define BUF_F    4256
#define K_STR    36
#define V_STR    40
#define P_STR    60
#define PM_OFF   8512
#define RB_OFF   12352
#define SMEM_F   15936           // 63744 bytes -> 3 blocks/SM, single wave

__global__ __launch_bounds__(128, 3) void attn_kernel()
{
    extern __shared__ float sm[];

    const int bx  = blockIdx.x;
    const int h   = bx / 49;
    const int p0  = (bx - h * 49) * 64;
    const int tid = threadIdx.x;
    const int w   = tid >> 5;
    const int ln  = tid & 31;
    const int g   = ln >> 2;          // 0..7
    const int t   = ln & 3;           // 0..3
    const int wq0 = w * 16;
    const int hbase = h * N_POS;

    const unsigned sm_u32 = (unsigned)__cvta_generic_to_shared(sm);

    // ---- rb tile [kr][q] (transposed from g_rowb[p][kr]) ------------------
    {
        const float* src = &g_rowb[(hbase + p0) * HW];
        for (int i = tid; i < 64 * HW; i += 128) {
            int q = i / HW, kr = i - q * HW;
            sm[RB_OFF + kr * 64 + q] = src[i];
        }
    }

    // ---- Q fragments (x INV), single tf32 ---------------------------------
    unsigned qh[4][4];
    {
        const float* Q0 = &g_q[(hbase + p0 + wq0 + g) * MIDC];
        const float* Q8 = Q0 + 8 * MIDC;
#pragma unroll
        for (int kc = 0; kc < 4; kc++) {
            qh[kc][0] = f2tf(Q0[8 * kc + t]     * INV);
            qh[kc][1] = f2tf(Q8[8 * kc + t]     * INV);
            qh[kc][2] = f2tf(Q0[8 * kc + t + 4] * INV);
            qh[kc][3] = f2tf(Q8[8 * kc + t + 4] * INV);
        }
    }

    // ---- column-bias registers matching D-fragment layout -----------------
    float cbr[7][4];
    {
        const float* C0 = &g_colb[(hbase + p0 + wq0 + g) * HW];
        const float* C8 = C0 + 8 * HW;
#pragma unroll
        for (int nt = 0; nt < 7; nt++) {
            int c0 = 8 * nt + 2 * t;
            cbr[nt][0] = C0[c0];     cbr[nt][1] = C0[c0 + 1];
            cbr[nt][2] = C8[c0];     cbr[nt][3] = C8[c0 + 1];
        }
    }

    float Oa[4][4], Ob[4][4];
#pragma unroll
    for (int mt = 0; mt < 4; mt++)
#pragma unroll
        for (int j = 0; j < 4; j++) { Oa[mt][j] = 0.f; Ob[mt][j] = 0.f; }
    float lsum0 = 0.f, lsum1 = 0.f;

    // ---- async tile loader (K + V, 896 x 16B) -----------------------------
    auto load_tile = [&](int kr, int buf) {
        const int bb = buf * BUF_F;
        const int gbase = (hbase + kr * HW) * MIDC;
#pragma unroll 4
        for (int i = tid; i < 896; i += 128) {
            int sec = i >= 448;
            int j   = sec ? i - 448 : i;
            int l   = j >> 3, c = (j & 7) << 2;
            const float* src;
            int dstf;
            if (!sec) { src = g_k + gbase + l * MIDC + c; dstf = bb + l * K_STR + c; }
            else      { src = g_v + gbase + l * MIDC + c; dstf = bb + 2016 + l * V_STR + c; }
            CP_ASYNC16(sm_u32 + dstf * 4, src);
        }
        CP_COMMIT();
    };

    load_tile(0, 0);

    for (int kr = 0; kr < HW; kr++) {
        const int buf = kr & 1;
        CP_WAIT0();
        __syncthreads();
        if (kr + 1 < HW) load_tile(kr + 1, buf ^ 1);

        const unsigned* Ku = (const unsigned*)(sm + buf * BUF_F);
        const unsigned* Vu = (const unsigned*)(sm + buf * BUF_F + 2016);
        float* Pm = sm + PM_OFF;

        const float rb0 = sm[RB_OFF + kr * 64 + wq0 + g];
        const float rb1 = sm[RB_OFF + kr * 64 + wq0 + g + 8];

        // ---- S = Q K^T + biases; P = exp(S) -------------------------------
#pragma unroll
        for (int nt = 0; nt < 7; nt++) {
            const int l0 = 8 * nt;
            float d0 = 0.f, d1 = 0.f, d2 = 0.f, d3 = 0.f;
#pragma unroll
            for (int kc = 0; kc < 4; kc++) {
                unsigned b0 = Ku[(l0 + g) * K_STR + 8 * kc + t];
                unsigned b1 = Ku[(l0 + g) * K_STR + 8 * kc + t + 4];
                mma_tf32(d0, d1, d2, d3,
                         qh[kc][0], qh[kc][1], qh[kc][2], qh[kc][3], b0, b1);
            }
            float pz0 = __expf(d0 + rb0 + cbr[nt][0]);
            float pz1 = __expf(d1 + rb0 + cbr[nt][1]);
            float pz2 = __expf(d2 + rb1 + cbr[nt][2]);
            float pz3 = __expf(d3 + rb1 + cbr[nt][3]);
            lsum0 += pz0 + pz1;
            lsum1 += pz2 + pz3;
            *(float2*)&Pm[(wq0 + g)     * P_STR + l0 + 2 * t] = make_float2(pz0, pz1);
            *(float2*)&Pm[(wq0 + g + 8) * P_STR + l0 + 2 * t] = make_float2(pz2, pz3);
        }

        __syncwarp();

        // ---- O += P V (single tf32, alternating accumulator banks) --------
#pragma unroll
        for (int kc = 0; kc < 7; kc++) {
            const int l0 = 8 * kc;
            unsigned ph[4];
            ph[0] = f2tf(Pm[(wq0 + g)     * P_STR + l0 + t]);
            ph[1] = f2tf(Pm[(wq0 + g + 8) * P_STR + l0 + t]);
            ph[2] = f2tf(Pm[(wq0 + g)     * P_STR + l0 + t + 4]);
            ph[3] = f2tf(Pm[(wq0 + g + 8) * P_STR + l0 + t + 4]);
            float (*acc)[4] = (kc & 1) ? Ob : Oa;
#pragma unroll
            for (int mt = 0; mt < 4; mt++) {
                unsigned b0 = Vu[(l0 + t)     * V_STR + 8 * mt + g];
                unsigned b1 = Vu[(l0 + t + 4) * V_STR + 8 * mt + g];
                mma_tf32(acc[mt][0], acc[mt][1], acc[mt][2], acc[mt][3],
                         ph[0], ph[1], ph[2], ph[3], b0, b1);
            }
        }
    }

    // ---- normalize + store -------------------------------------------------
    lsum0 += __shfl_xor_sync(0xffffffffu, lsum0, 1);
    lsum0 += __shfl_xor_sync(0xffffffffu, lsum0, 2);
    lsum1 += __shfl_xor_sync(0xffffffffu, lsum1, 1);
    lsum1 += __shfl_xor_sync(0xffffffffu, lsum1, 2);
    const float rinv0 = 1.0f / lsum0;
    const float rinv1 = 1.0f / lsum1;

    const int pA = p0 + wq0 + g;
#pragma unroll
    for (int mt = 0; mt < 4; mt++) {
        int c0 = 8 * mt + 2 * t;
        g_o[(c0       * HEADS + h) * N_POS + pA]     = (Oa[mt][0] + Ob[mt][0]) * rinv0;
        g_o[((c0 + 1) * HEADS + h) * N_POS + pA]     = (Oa[mt][1] + Ob[mt][1]) * rinv0;
        g_o[(c0       * HEADS + h) * N_POS + pA + 8] = (Oa[mt][2] + Ob[mt][2]) * rinv1;
        g_o[((c0 + 1) * HEADS + h) * N_POS + pA + 8] = (Oa[mt][3] + Ob[mt][3]) * rinv1;
    }
}

// ---------------- Kernel 4: output projection, co-split for occupancy -------
__global__ __launch_bounds__(256) void out_kernel(
    const float* __restrict__ Wo, const float* __restrict__ bo,
    float* __restrict__ out)
{
    __shared__ float Xs[64 * 64];
    __shared__ float Ws[16 * 68];

    const int p0  = blockIdx.x * 64;
    const int co0 = blockIdx.y * 16;
    const int tid = threadIdx.x;
    const int tx = tid & 15, ty = tid >> 4;

    float acc[4] = {0.f, 0.f, 0.f, 0.f};

    for (int kc = 0; kc < 256; kc += 64) {
        __syncthreads();
        for (int i = tid; i < 64 * 16; i += 256) {
            int r = i >> 4, c4 = (i & 15) * 4;
            *(float4*)&Xs[r * 64 + c4] =
                *(const float4*)&g_o[(kc + r) * N_POS + p0 + c4];
        }
        {
            int r = tid >> 4, c4 = (tid & 15) * 4;
            *(float4*)&Ws[r * 68 + c4] =
                *(const float4*)&Wo[(co0 + r) * 256 + kc + c4];
        }
        __syncthreads();
#pragma unroll 8
        for (int kk = 0; kk < 64; kk++) {
            float a = Ws[ty * 68 + kk];
            float4 b = *(const float4*)&Xs[kk * 64 + tx * 4];
            acc[0] += a * b.x;
            acc[1] += a * b.y;
            acc[2] += a * b.z;
            acc[3] += a * b.w;
        }
    }

    float bv_ = bo[co0 + ty];
#pragma unroll
    for (int j = 0; j < 4; j++)
        out[(co0 + ty) * N_POS + p0 + tx * 4 + j] = acc[j] + bv_;
}

// ---------------- launch -----------------------------------------------------
extern "C" void kernel_launch(void* const* d_in, const int* in_sizes, int n_in,
                              void* d_out, int out_size)
{
    const float* x    = (const float*)d_in[0];
    const float* Wq   = (const float*)d_in[1];
    const float* bq   = (const float*)d_in[2];
    const float* Wk   = (const float*)d_in[3];
    const float* bk   = (const float*)d_in[4];
    const float* Wv   = (const float*)d_in[5];
    const float* bv   = (const float*)d_in[6];
    const float* Wo   = (const float*)d_in[7];
    const float* bo   = (const float*)d_in[8];
    const float* rowT = (const float*)d_in[9];
    const float* colT = (const float*)d_in[10];

    cudaFuncSetAttribute(attn_kernel,
                         cudaFuncAttributeMaxDynamicSharedMemorySize,
                         SMEM_F * 4);

    qkv_kernel<<<dim3(49, 12), 256>>>(x, Wq, bq, Wk, bk, Wv, bv);
    bias_kernel<<<10976, 256>>>(rowT, colT);
    attn_kernel<<<392, 128, SMEM_F * 4>>>();
    out_kernel<<<dim3(49, 4), 256>>>(Wo, bo, (float*)d_out);
}

// round 8
// speedup vs baseline: 1.1923x; 1.1923x over previous
#include <cuda_runtime.h>
#include <cuda_fp16.h>
#include <math_constants.h>
#include <cstdint>

#define N_POS 3136
#define HW    56
#define MIDC  32
#define HEADS 8
#define INV   0.125f   // 1/sqrt(64)

// ---------------- scratch (global, no allocation in kernel_launch) ----------
__device__ float  g_q [HEADS * N_POS * MIDC];   // [h][p][m] fp32 (bias kernel reads)
__device__ __half g_k [HEADS * N_POS * MIDC];   // [h][p][m] fp16
__device__ __half g_vT[HEADS * MIDC * N_POS];   // [h][m][p] fp16 (transposed V)
__device__ float g_rowb[HEADS * N_POS * HW];    // inv-scaled row bias [h][p][k]
__device__ float g_colb[HEADS * N_POS * HW];    // inv-scaled col bias [h][p][l]
__device__ float g_o[MIDC * HEADS * N_POS];     // [channel = m*8+h][p]

// ---------------- helpers ----------------------------------------------------
__device__ __forceinline__ uint32_t pkh2(float lo, float hi) {
    uint32_t r;                       // d.hi = first src, d.lo = second src
    asm("cvt.rn.f16x2.f32 %0, %1, %2;" : "=r"(r) : "f"(hi), "f"(lo));
    return r;
}
__device__ __forceinline__ void mma_f16(
    float& d0, float& d1, float& d2, float& d3,
    uint32_t a0, uint32_t a1, uint32_t a2, uint32_t a3,
    uint32_t b0, uint32_t b1)
{
    asm("mma.sync.aligned.m16n8k16.row.col.f32.f16.f16.f32 "
        "{%0,%1,%2,%3}, {%4,%5,%6,%7}, {%8,%9}, {%0,%1,%2,%3};"
        : "+f"(d0), "+f"(d1), "+f"(d2), "+f"(d3)
        : "r"(a0), "r"(a1), "r"(a2), "r"(a3), "r"(b0), "r"(b1));
}

#define CP_ASYNC16(dst_smem, src) \
    asm volatile("cp.async.cg.shared.global [%0], [%1], 16;" \
                 :: "r"((unsigned)(dst_smem)), "l"(src))
#define CP_COMMIT()  asm volatile("cp.async.commit_group;")
#define CP_WAIT0()   asm volatile("cp.async.wait_group 0;" ::: "memory")

// ---------------- Kernel 1: fused QKV projection ----------------------------
__global__ __launch_bounds__(256) void qkv_kernel(
    const float* __restrict__ x,
    const float* __restrict__ Wq, const float* __restrict__ bq,
    const float* __restrict__ Wk, const float* __restrict__ bk,
    const float* __restrict__ Wv, const float* __restrict__ bv)
{
    __shared__ float Xs[64 * 64];
    __shared__ float Ws[64 * 68];

    const int p0  = blockIdx.x * 64;
    const int by  = blockIdx.y;        // 0..11
    const int mat = by >> 2;           // 0=q 1=k 2=v
    const int dl0 = (by & 3) * 64;

    const float* W    = (mat == 0) ? Wq : (mat == 1) ? Wk : Wv;
    const float* bias = (mat == 0) ? bq : (mat == 1) ? bk : bv;

    const int tid = threadIdx.x;
    for (int i = tid; i < 64 * 16; i += 256) {
        int r = i >> 4, c4 = (i & 15) * 4;
        *(float4*)&Xs[r * 64 + c4] = *(const float4*)&x[r * N_POS + p0 + c4];
        *(float4*)&Ws[r * 68 + c4] = *(const float4*)&W[(dl0 + r) * 64 + c4];
    }
    __syncthreads();

    const int tx = tid & 15, ty = tid >> 4;
    float acc[4][4];
#pragma unroll
    for (int i = 0; i < 4; i++)
#pragma unroll
        for (int j = 0; j < 4; j++) acc[i][j] = 0.f;

#pragma unroll 8
    for (int kk = 0; kk < 64; kk++) {
        float a[4];
#pragma unroll
        for (int i = 0; i < 4; i++) a[i] = Ws[(ty * 4 + i) * 68 + kk];
        float4 b = *(const float4*)&Xs[kk * 64 + tx * 4];
#pragma unroll
        for (int i = 0; i < 4; i++) {
            acc[i][0] += a[i] * b.x; acc[i][1] += a[i] * b.y;
            acc[i][2] += a[i] * b.z; acc[i][3] += a[i] * b.w;
        }
    }

#pragma unroll
    for (int i = 0; i < 4; i++) {
        int d = dl0 + ty * 4 + i;
        float bv_ = bias[d];
        int h = d & 7, m = d >> 3;       // d = m*8 + h
#pragma unroll
        for (int j = 0; j < 4; j++) {
            int p = p0 + tx * 4 + j;
            float val = acc[i][j] + bv_;
            if (mat == 0)      g_q [(h * N_POS + p) * MIDC + m] = val;
            else if (mat == 1) g_k [(h * N_POS + p) * MIDC + m] = __float2half(val);
            else               g_vT[(h * MIDC + m) * N_POS + p] = __float2half(val);
        }
    }
}

// ---------------- Kernel 2: relative-position bias precompute ---------------
__global__ __launch_bounds__(256) void bias_kernel(
    const float* __restrict__ rowT, const float* __restrict__ colT)
{
    int idx = blockIdx.x * 256 + threadIdx.x;
    int h   = idx / (N_POS * 112);
    int rem = idx - h * (N_POS * 112);
    int p   = rem / 112;
    int t   = rem - p * 112;
    const float* Qp = &g_q[(h * N_POS + p) * MIDC];

    if (t < HW) {
        int i = p / HW;
        const float* tr = &rowT[(t - i + 55) * 16];
        float acc = 0.f;
#pragma unroll
        for (int m = 0; m < 16; m++) acc += Qp[m] * tr[m];
        g_rowb[(h * N_POS + p) * HW + t] = acc * INV;
    } else {
        int l = t - HW, j = p % HW;
        const float* tc = &colT[(l - j + 55) * 16];
        float acc = 0.f;
#pragma unroll
        for (int m = 0; m < 16; m++) acc += Qp[16 + m] * tc[m];
        g_colb[(h * N_POS + p) * HW + l] = acc * INV;
    }
}

// ---------------- Kernel 3: fp16 m16n8k16 flash attention -------------------
// Block = 128 threads = 4 warps; warp w owns query rows [16w, 16w+16).
// smem layout (bytes):
//   K0 @0      : [56 keys][40 halves]   (4480 B; row = 20 words, conflict-free)
//   K1 @4480
//   V0 @8960   : [32 ch][72 halves]     (4608 B; V transposed: [ch][key])
//   V1 @13568
//   Pm @18176  : [64 q][72 halves]      (9216 B; cols 56..63 zero pad)
//   rb @27392  : [56 kr][64 q] f32      (14336 B)
#define KOFF0 0
#define KOFF1 4480
#define VOFF0 8960
#define VOFF1 13568
#define PMOFF 18176
#define RBOFF 27392
#define SMEMB 41728

__global__ __launch_bounds__(128, 3) void attn_kernel()
{
    extern __shared__ char smc[];
    float* smf = (float*)smc;

    const int bx  = blockIdx.x;
    const int h   = bx / 49;
    const int p0  = (bx - h * 49) * 64;
    const int tid = threadIdx.x;
    const int w   = tid >> 5;
    const int ln  = tid & 31;
    const int g   = ln >> 2;          // 0..7
    const int t   = ln & 3;           // 0..3
    const int wq0 = w * 16;
    const int hbase = h * N_POS;

    const unsigned sm_u32 = (unsigned)__cvta_generic_to_shared(smc);

    // ---- zero pads: V cols 56..63 (both bufs), P cols 56..63 --------------
    for (int i = tid; i < 256; i += 128) {          // V pads: 2 bufs x 32 rows x 4 words
        int b = i >> 7, j = i & 127;
        int m = j >> 2, c = j & 3;
        *(uint32_t*)(smc + (b ? VOFF1 : VOFF0) + m * 144 + 112 + c * 4) = 0;
    }
    for (int i = tid; i < 256; i += 128) {          // P pads: 64 rows x 4 words
        int q = i >> 2, c = i & 3;
        *(uint32_t*)(smc + PMOFF + q * 144 + 112 + c * 4) = 0;
    }

    // ---- rb tile [kr][q] (transposed from g_rowb[p][kr]) ------------------
    {
        const float* src = &g_rowb[(hbase + p0) * HW];
        float* rbs = smf + RBOFF / 4;
        for (int i = tid; i < 64 * HW; i += 128) {
            int q = i / HW, kr = i - q * HW;
            rbs[kr * 64 + q] = src[i];
        }
    }

    // ---- Q fragments (x INV) as packed fp16 -------------------------------
    // qa[kc][0]=(g,2t,2t+1) qa[kc][1]=(g+8,..) qa[kc][2]=(g,2t+8..) qa[kc][3]=(g+8,..)
    uint32_t qa[2][4];
    {
        const float* Q0 = &g_q[(hbase + p0 + wq0 + g) * MIDC];
        const float* Q8 = Q0 + 8 * MIDC;
#pragma unroll
        for (int kc = 0; kc < 2; kc++) {
            int c0 = 16 * kc + 2 * t;
            qa[kc][0] = pkh2(Q0[c0]     * INV, Q0[c0 + 1] * INV);
            qa[kc][1] = pkh2(Q8[c0]     * INV, Q8[c0 + 1] * INV);
            qa[kc][2] = pkh2(Q0[c0 + 8] * INV, Q0[c0 + 9] * INV);
            qa[kc][3] = pkh2(Q8[c0 + 8] * INV, Q8[c0 + 9] * INV);
        }
    }

    // ---- column-bias registers matching D-fragment layout -----------------
    float cbr[7][4];
    {
        const float* C0 = &g_colb[(hbase + p0 + wq0 + g) * HW];
        const float* C8 = C0 + 8 * HW;
#pragma unroll
        for (int nt = 0; nt < 7; nt++) {
            int c0 = 8 * nt + 2 * t;
            cbr[nt][0] = C0[c0]; cbr[nt][1] = C0[c0 + 1];
            cbr[nt][2] = C8[c0]; cbr[nt][3] = C8[c0 + 1];
        }
    }

    float Oa[4][4];
#pragma unroll
    for (int mt = 0; mt < 4; mt++)
#pragma unroll
        for (int j = 0; j < 4; j++) Oa[mt][j] = 0.f;
    float lsum0 = 0.f, lsum1 = 0.f;

    // ---- async tile loader: K 224x16B + V^T 224x16B -----------------------
    auto load_tile = [&](int kr, int buf) {
        const uint32_t kof = sm_u32 + (buf ? KOFF1 : KOFF0);
        const uint32_t vof = sm_u32 + (buf ? VOFF1 : VOFF0);
        const __half* Kg = g_k  + (hbase + kr * HW) * MIDC;
        const __half* Vg = g_vT + h * MIDC * N_POS + kr * HW;
#pragma unroll 4
        for (int i = tid; i < 448; i += 128) {
            if (i < 224) {
                int l = i >> 2, c = i & 3;
                CP_ASYNC16(kof + l * 80 + c * 16, Kg + l * 32 + c * 8);
            } else {
                int j = i - 224;
                int m = j / 7, t7 = j - m * 7;
                CP_ASYNC16(vof + m * 144 + t7 * 16, Vg + m * N_POS + t7 * 8);
            }
        }
        CP_COMMIT();
    };

    load_tile(0, 0);

    for (int kr = 0; kr < HW; kr++) {
        const int buf = kr & 1;
        CP_WAIT0();
        __syncthreads();
        if (kr + 1 < HW) load_tile(kr + 1, buf ^ 1);

        const uint32_t* Ku = (const uint32_t*)(smc + (buf ? KOFF1 : KOFF0));
        const uint32_t* Vw = (const uint32_t*)(smc + (buf ? VOFF1 : VOFF0));
        uint32_t* Pw = (uint32_t*)(smc + PMOFF);

        const float rb0 = smf[RBOFF / 4 + kr * 64 + wq0 + g];
        const float rb1 = smf[RBOFF / 4 + kr * 64 + wq0 + g + 8];

        // ---- S = Q K^T + biases; P = exp(S) -> fp16 -----------------------
#pragma unroll
        for (int nt = 0; nt < 7; nt++) {
            const int l0 = 8 * nt;
            const uint32_t* krow = Ku + (l0 + g) * 20 + t;
            uint32_t b00 = krow[0], b01 = krow[4], b10 = krow[8], b11 = krow[12];
            float d0 = 0.f, d1 = 0.f, d2 = 0.f, d3 = 0.f;
            mma_f16(d0, d1, d2, d3, qa[0][0], qa[0][1], qa[0][2], qa[0][3], b00, b01);
            mma_f16(d0, d1, d2, d3, qa[1][0], qa[1][1], qa[1][2], qa[1][3], b10, b11);

            float pz0 = __expf(d0 + rb0 + cbr[nt][0]);
            float pz1 = __expf(d1 + rb0 + cbr[nt][1]);
            float pz2 = __expf(d2 + rb1 + cbr[nt][2]);
            float pz3 = __expf(d3 + rb1 + cbr[nt][3]);
            lsum0 += pz0 + pz1;
            lsum1 += pz2 + pz3;
            Pw[(wq0 + g)     * 36 + 4 * nt + t] = pkh2(pz0, pz1);
            Pw[(wq0 + g + 8) * 36 + 4 * nt + t] = pkh2(pz2, pz3);
        }

        __syncwarp();

        // ---- O += P V  (4 k16 chunks over 64 padded keys) -----------------
#pragma unroll
        for (int kc = 0; kc < 4; kc++) {
            const uint32_t* pr0 = Pw + (wq0 + g)     * 36 + 8 * kc + t;
            const uint32_t* pr8 = Pw + (wq0 + g + 8) * 36 + 8 * kc + t;
            uint32_t a0 = pr0[0], a1 = pr8[0], a2 = pr0[4], a3 = pr8[4];
#pragma unroll
            for (int mt = 0; mt < 4; mt++) {
                const uint32_t* vrow = Vw + (8 * mt + g) * 36 + 8 * kc + t;
                mma_f16(Oa[mt][0], Oa[mt][1], Oa[mt][2], Oa[mt][3],
                        a0, a1, a2, a3, vrow[0], vrow[4]);
            }
        }
    }

    // ---- normalize + store -------------------------------------------------
    lsum0 += __shfl_xor_sync(0xffffffffu, lsum0, 1);
    lsum0 += __shfl_xor_sync(0xffffffffu, lsum0, 2);
    lsum1 += __shfl_xor_sync(0xffffffffu, lsum1, 1);
    lsum1 += __shfl_xor_sync(0xffffffffu, lsum1, 2);
    const float rinv0 = 1.0f / lsum0;
    const float rinv1 = 1.0f / lsum1;

    const int pA = p0 + wq0 + g;
#pragma unroll
    for (int mt = 0; mt < 4; mt++) {
        int c0 = 8 * mt + 2 * t;
        g_o[(c0       * HEADS + h) * N_POS + pA]     = Oa[mt][0] * rinv0;
        g_o[((c0 + 1) * HEADS + h) * N_POS + pA]     = Oa[mt][1] * rinv0;
        g_o[(c0       * HEADS + h) * N_POS + pA + 8] = Oa[mt][2] * rinv1;
        g_o[((c0 + 1) * HEADS + h) * N_POS + pA + 8] = Oa[mt][3] * rinv1;
    }
}

// ---------------- Kernel 4: output projection -------------------------------
__global__ __launch_bounds__(256) void out_kernel(
    const float* __restrict__ Wo, const float* __restrict__ bo,
    float* __restrict__ out)
{
    __shared__ float Xs[64 * 64];
    __shared__ float Ws[16 * 68];

    const int p0  = blockIdx.x * 64;
    const int co0 = blockIdx.y * 16;
    const int tid = threadIdx.x;
    const int tx = tid & 15, ty = tid >> 4;
    float acc[4] = {0.f, 0.f, 0.f, 0.f};

    for (int kc = 0; kc < 256; kc += 64) {
        __syncthreads();
        for (int i = tid; i < 64 * 16; i += 256) {
            int r = i >> 4, c4 = (i & 15) * 4;
            *(float4*)&Xs[r * 64 + c4] = *(const float4*)&g_o[(kc + r) * N_POS + p0 + c4];
        }
        {
            int r = tid >> 4, c4 = (tid & 15) * 4;
            *(float4*)&Ws[r * 68 + c4] = *(const float4*)&Wo[(co0 + r) * 256 + kc + c4];
        }
        __syncthreads();
#pragma unroll 8
        for (int kk = 0; kk < 64; kk++) {
            float a = Ws[ty * 68 + kk];
            float4 b = *(const float4*)&Xs[kk * 64 + tx * 4];
            acc[0] += a * b.x; acc[1] += a * b.y; acc[2] += a * b.z; acc[3] += a * b.w;
        }
    }
    float bv_ = bo[co0 + ty];
#pragma unroll
    for (int j = 0; j < 4; j++)
        out[(co0 + ty) * N_POS + p0 + tx * 4 + j] = acc[j] + bv_;
}

// ---------------- launch -----------------------------------------------------
extern "C" void kernel_launch(void* const* d_in, const int* in_sizes, int n_in,
                              void* d_out, int out_size)
{
    const float* x    = (const float*)d_in[0];
    const float* Wq   = (const float*)d_in[1];
    const float* bq   = (const float*)d_in[2];
    const float* Wk   = (const float*)d_in[3];
    const float* bk   = (const float*)d_in[4];
    const float* Wv   = (const float*)d_in[5];
    const float* bv   = (const float*)d_in[6];
    const float* Wo   = (const float*)d_in[7];
    const float* bo   = (const float*)d_in[8];
    const float* rowT = (const float*)d_in[9];
    const float* colT = (const float*)d_in[10];

    cudaFuncSetAttribute(attn_kernel,
                         cudaFuncAttributeMaxDynamicSharedMemorySize, SMEMB);

    qkv_kernel<<<dim3(49, 12), 256>>>(x, Wq, bq, Wk, bk, Wv, bv);
    bias_kernel<<<10976, 256>>>(rowT, colT);
    attn_kernel<<<392, 128, SMEMB>>>();
    out_kernel<<<dim3(49, 4), 256>>>(Wo, bo, (float*)d_out);
}